// round 15
// baseline (speedup 1.0000x reference)
#include <cuda_runtime.h>
#include <cuda_fp16.h>
#include <math.h>
#include <stdint.h>

#define BB 8
#define TT 2048
#define DD 1024
#define HH 128
#define MM (BB*TT)

// ---------------- device-global scratch (allocation-guard safe) ------------
__device__ __half g_xf[MM*DD];              // x fp16
__device__ __half g_wf[3*HH*DD];            // W^T [mat][n][k], fp16
// fp16 attention operands
__device__ __half g_qh2[MM*HH];             // post-RoPE, scaled, fp16 hi
__device__ __half g_ql2[MM*HH];             // fp16 lo residual
__device__ __half g_kf[MM*HH];              // post-RoPE, fp16
__device__ __half g_vf[MM*HH];              // fp16
// split-KV partials: [z][b*TT+row]
__device__ float g_po[2*MM*HH];
__device__ float g_pm[2*MM];
__device__ float g_pl[2*MM];

// ---------------- PTX helpers (base sm_103-safe) ----------------------------
__device__ __forceinline__ uint32_t smem_u32(const void* p) {
    uint32_t a;
    asm("{ .reg .u64 t; cvta.to.shared.u64 t, %1; cvt.u32.u64 %0, t; }"
        : "=r"(a) : "l"(p));
    return a;
}

__device__ __forceinline__ void cp16(uint32_t saddr, const void* g) {
    asm volatile("cp.async.cg.shared.global [%0], [%1], 16;"
                 :: "r"(saddr), "l"(g) : "memory");
}
__device__ __forceinline__ void cp_commit() {
    asm volatile("cp.async.commit_group;" ::: "memory");
}
__device__ __forceinline__ void cp_wait0() {
    asm volatile("cp.async.wait_group 0;" ::: "memory");
}
__device__ __forceinline__ void cp_wait1() {
    asm volatile("cp.async.wait_group 1;" ::: "memory");
}

__device__ __forceinline__ void ldsm_x4(uint32_t& a0, uint32_t& a1,
                                        uint32_t& a2, uint32_t& a3, uint32_t addr) {
    asm volatile("ldmatrix.sync.aligned.m8n8.x4.shared.b16 {%0,%1,%2,%3}, [%4];"
                 : "=r"(a0), "=r"(a1), "=r"(a2), "=r"(a3) : "r"(addr));
}
__device__ __forceinline__ void ldsm_x4t(uint32_t& a0, uint32_t& a1,
                                         uint32_t& a2, uint32_t& a3, uint32_t addr) {
    asm volatile("ldmatrix.sync.aligned.m8n8.x4.trans.shared.b16 {%0,%1,%2,%3}, [%4];"
                 : "=r"(a0), "=r"(a1), "=r"(a2), "=r"(a3) : "r"(addr));
}

// fp16 mma
__device__ __forceinline__ void mma16816h(float* c, const uint32_t* a,
                                          uint32_t b0, uint32_t b1) {
    asm volatile(
        "mma.sync.aligned.m16n8k16.row.col.f32.f16.f16.f32 "
        "{%0,%1,%2,%3}, {%4,%5,%6,%7}, {%8,%9}, {%0,%1,%2,%3};"
        : "+f"(c[0]), "+f"(c[1]), "+f"(c[2]), "+f"(c[3])
        : "r"(a[0]), "r"(a[1]), "r"(a[2]), "r"(a[3]), "r"(b0), "r"(b1));
}

__device__ __forceinline__ uint32_t pack_h2(float a, float b) {
    __half2 h = __floats2half2_rn(a, b);      // x=a (low), y=b (high)
    return *reinterpret_cast<uint32_t*>(&h);
}

// ---------------------------------------------------------------------------
// fp32 -> fp16 conversions
// ---------------------------------------------------------------------------
__global__ __launch_bounds__(256) void convert_x_kernel(const float* __restrict__ x)
{
    int i = blockIdx.x * 256 + threadIdx.x;          // over MM*DD/4
    float4 v = ((const float4*)x)[i];
    uint32_t* ph = (uint32_t*)g_xf;
    ph[2*i]   = pack_h2(v.x, v.y);
    ph[2*i+1] = pack_h2(v.z, v.w);
}

__global__ __launch_bounds__(256) void convert_w_kernel(
    const float* __restrict__ Wq, const float* __restrict__ Wk,
    const float* __restrict__ Wv)
{
    int mat = blockIdx.y;
    const float* __restrict__ W = (mat == 0) ? Wq : ((mat == 1) ? Wk : Wv);
    int i = blockIdx.x * 256 + threadIdx.x;          // 0 .. DD*HH-1
    int k = i >> 7;
    int n = i & 127;
    g_wf[(size_t)mat * HH * DD + (size_t)n * DD + k] = __float2half_rn(W[i]);
}

// ---------------------------------------------------------------------------
// QKV projection: fp16 single-pass mma (xf·Wf) + RoPE epilogue, fp16 outputs.
// grid=(128,3), 256 threads. smem: 2 buffers x (2 tiles x 128 x QP halves)
// ---------------------------------------------------------------------------
#define QP 72
#define QBUF (2*128*QP)

__global__ __launch_bounds__(256) void qkv_mma_kernel()
{
    extern __shared__ __half smq[];

    const int tid = threadIdx.x;
    const int w   = tid >> 5;
    const int lane= tid & 31;
    const int mat = blockIdx.y;
    const int m0  = blockIdx.x * 128;

    const __half* __restrict__ Xf = g_xf + (size_t)m0 * DD;
    const __half* __restrict__ Bw = g_wf + (size_t)mat * HH * DD;

    float c[16][4];
#pragma unroll
    for (int nt = 0; nt < 16; nt++)
#pragma unroll
        for (int e = 0; e < 4; e++) c[nt][e] = 0.0f;

    auto stageq = [&](int buf, int kc) {
        const int kb = kc * 64;
        __half* base = smq + buf * QBUF;
        const __half* srcs[2] = {Xf, Bw};
#pragma unroll
        for (int t = 0; t < 2; t++) {
#pragma unroll
            for (int itr = 0; itr < 4; itr++) {
                int idx = itr * 256 + tid;
                int row = idx >> 3, seg = idx & 7;
                cp16(smem_u32(base + t*128*QP + row*QP + seg*8),
                     srcs[t] + (size_t)row * DD + kb + seg*8);
            }
        }
    };

    stageq(0, 0);
    cp_commit();

    const int brr = (lane & 7) + ((lane >> 4) & 1) * 8;
    const int bcc = (lane & 8);

    for (int kc = 0; kc < 16; kc++) {
        if (kc + 1 < 16) { stageq((kc + 1) & 1, kc + 1); cp_commit(); cp_wait1(); }
        else             { cp_wait0(); }
        __syncthreads();

        __half* base = smq + (kc & 1) * QBUF;
        __half* sxf = base;
        __half* swf = base + 128*QP;

        uint32_t ah[4][4];
        {
            int r = w*16 + (lane & 7) + ((lane >> 3) & 1) * 8;
            int cg = ((lane >> 4) & 1) * 8;
#pragma unroll
            for (int kt = 0; kt < 4; kt++) {
                ldsm_x4(ah[kt][0], ah[kt][1], ah[kt][2], ah[kt][3],
                        smem_u32(sxf + r*QP + kt*16 + cg));
            }
        }

#pragma unroll
        for (int nt2 = 0; nt2 < 8; nt2++) {
#pragma unroll
            for (int kt = 0; kt < 4; kt++) {
                int br = nt2*16 + brr;
                int bc = kt*16 + bcc;
                uint32_t b4[4];
                ldsm_x4(b4[0], b4[1], b4[2], b4[3], smem_u32(swf + br*QP + bc));
                mma16816h(c[2*nt2],   ah[kt], b4[0], b4[1]);
                mma16816h(c[2*nt2+1], ah[kt], b4[2], b4[3]);
            }
        }
        __syncthreads();
    }

    const float qs = (mat == 0) ? 0.08838834764831845f : 1.0f;
    const int rloc = w*16 + (lane >> 2);
    const int m_lo = m0 + rloc;
    const int m_hi = m_lo + 8;
    const float pos0 = (float)(m_lo & (TT - 1));
    const float pos1 = (float)(m_hi & (TT - 1));

#pragma unroll
    for (int nt = 0; nt < 16; nt++) {
        int col = nt*8 + (lane & 3)*2;
        float e00 = c[nt][0]*qs, e01 = c[nt][1]*qs;
        float e10 = c[nt][2]*qs, e11 = c[nt][3]*qs;
        if (mat < 2) {
            int p = col >> 1;
            float freq = exp2f(-(float)p * (13.287712379549449f / 64.0f));
            float s0, c0v, s1, c1v;
            sincosf(pos0 * freq, &s0, &c0v);
            sincosf(pos1 * freq, &s1, &c1v);
            float t0 = e00*c0v - e01*s0, t1 = e00*s0 + e01*c0v;
            e00 = t0; e01 = t1;
            t0 = e10*c1v - e11*s1; t1 = e10*s1 + e11*c1v;
            e10 = t0; e11 = t1;
        }
        if (mat == 0) {
            // q: fp16 hi + lo residual
            float h00 = __half2float(__float2half_rn(e00));
            float h01 = __half2float(__float2half_rn(e01));
            float h10 = __half2float(__float2half_rn(e10));
            float h11 = __half2float(__float2half_rn(e11));
            *(uint32_t*)(g_qh2 + (size_t)m_lo*HH + col) = pack_h2(h00, h01);
            *(uint32_t*)(g_ql2 + (size_t)m_lo*HH + col) = pack_h2(e00 - h00, e01 - h01);
            *(uint32_t*)(g_qh2 + (size_t)m_hi*HH + col) = pack_h2(h10, h11);
            *(uint32_t*)(g_ql2 + (size_t)m_hi*HH + col) = pack_h2(e10 - h10, e11 - h11);
        } else {
            __half* dst = (mat == 1) ? g_kf : g_vf;
            *(uint32_t*)(dst + (size_t)m_lo*HH + col) = pack_h2(e00, e01);
            *(uint32_t*)(dst + (size_t)m_hi*HH + col) = pack_h2(e10, e11);
        }
    }
}

// ---------------------------------------------------------------------------
// Causal flash attention: fp16 2-pass, split-KV z=2, cp.async double-buffer.
// (unchanged from round 13)
// grid=(16,8,2), 256 threads, q-tile 128, k-tile 64.
// smem: 2 buffers x (2 tiles x 64 x AP halves) = 69632 B
// ---------------------------------------------------------------------------
#define AP 136
#define ABUF (2*64*AP)

__global__ __launch_bounds__(256) void attn_kernel()
{
    extern __shared__ __half sma[];

    const int tid = threadIdx.x;
    const int w   = tid >> 5;
    const int lane= tid & 31;
    const int b   = blockIdx.y;
    const int z   = blockIdx.z;
    const int i0  = (gridDim.x - 1 - blockIdx.x) * 128;

    const int rloc = w*16 + (lane >> 2);
    const size_t qrow = (size_t)(b*TT + i0 + rloc) * HH;

    uint32_t qh[8][4], ql[8][4];
#pragma unroll
    for (int kt = 0; kt < 8; kt++) {
        int cb = kt*16 + (lane & 3)*2;
        qh[kt][0] = *(const uint32_t*)(g_qh2 + qrow + cb);
        qh[kt][1] = *(const uint32_t*)(g_qh2 + qrow + 8*HH + cb);
        qh[kt][2] = *(const uint32_t*)(g_qh2 + qrow + cb + 8);
        qh[kt][3] = *(const uint32_t*)(g_qh2 + qrow + 8*HH + cb + 8);
        ql[kt][0] = *(const uint32_t*)(g_ql2 + qrow + cb);
        ql[kt][1] = *(const uint32_t*)(g_ql2 + qrow + 8*HH + cb);
        ql[kt][2] = *(const uint32_t*)(g_ql2 + qrow + cb + 8);
        ql[kt][3] = *(const uint32_t*)(g_ql2 + qrow + 8*HH + cb + 8);
    }

    float o[16][4];
#pragma unroll
    for (int nt = 0; nt < 16; nt++)
#pragma unroll
        for (int e = 0; e < 4; e++) o[nt][e] = 0.0f;
    float mrow0 = -1e30f, mrow1 = -1e30f, l0 = 0.0f, l1 = 0.0f;

    const int ntiles = i0/64 + 2;            // even
    const int htiles = ntiles >> 1;
    const int jt0 = z * htiles;
    const int n = htiles;

    auto stagea = [&](int buf, int jt) {
        const size_t gbase = (size_t)(b*TT + jt*64) * HH;
        __half* base = sma + buf * ABUF;
        const __half* srcs[2] = {g_kf + gbase, g_vf + gbase};
#pragma unroll
        for (int t = 0; t < 2; t++) {
#pragma unroll
            for (int itr = 0; itr < 4; itr++) {
                int idx = itr*256 + tid;
                int row = idx >> 4, seg = idx & 15;
                cp16(smem_u32(base + t*64*AP + row*AP + seg*8),
                     srcs[t] + (size_t)row*HH + seg*8);
            }
        }
    };

    stagea(0, jt0);
    cp_commit();

    const int brr = (lane & 7) + ((lane >> 4) & 1) * 8;   // B-frag row offset
    const int bcc = (lane & 8);                            // B-frag col offset
    const int vrr = (lane & 7) + (lane & 8);               // V-frag row offset
    const int vcc = ((lane >> 4) & 1) * 8;                 // V-frag col offset

    for (int i = 0; i < n; i++) {
        const int jt = jt0 + i;
        const int j0 = jt * 64;

        if (i + 1 < n) { stagea((i + 1) & 1, jt + 1); cp_commit(); cp_wait1(); }
        else           { cp_wait0(); }
        __syncthreads();

        __half* base = sma + (i & 1) * ABUF;
        __half* kh = base;
        __half* vh = base + 64*AP;

        float s[8][4];
#pragma unroll
        for (int nt = 0; nt < 8; nt++)
#pragma unroll
            for (int e = 0; e < 4; e++) s[nt][e] = 0.0f;

        // S = (Qh + Ql) Kf^T : 2-pass fp16
#pragma unroll
        for (int nt2 = 0; nt2 < 4; nt2++) {
#pragma unroll
            for (int kt = 0; kt < 8; kt++) {
                int br = nt2*16 + brr;
                int bc = kt*16 + bcc;
                uint32_t b4[4];
                ldsm_x4(b4[0], b4[1], b4[2], b4[3], smem_u32(kh + br*AP + bc));
                mma16816h(s[2*nt2],   qh[kt], b4[0], b4[1]);
                mma16816h(s[2*nt2+1], qh[kt], b4[2], b4[3]);
                mma16816h(s[2*nt2],   ql[kt], b4[0], b4[1]);
                mma16816h(s[2*nt2+1], ql[kt], b4[2], b4[3]);
            }
        }

        if (j0 >= i0) {
            int row0 = i0 + rloc;
            int row1 = row0 + 8;
#pragma unroll
            for (int nt = 0; nt < 8; nt++) {
                int colb = j0 + nt*8 + (lane & 3)*2;
                if (colb     > row0) s[nt][0] = -1e30f;
                if (colb + 1 > row0) s[nt][1] = -1e30f;
                if (colb     > row1) s[nt][2] = -1e30f;
                if (colb + 1 > row1) s[nt][3] = -1e30f;
            }
        }

        float rm0 = -1e30f, rm1 = -1e30f;
#pragma unroll
        for (int nt = 0; nt < 8; nt++) {
            rm0 = fmaxf(rm0, fmaxf(s[nt][0], s[nt][1]));
            rm1 = fmaxf(rm1, fmaxf(s[nt][2], s[nt][3]));
        }
        rm0 = fmaxf(rm0, __shfl_xor_sync(0xffffffffu, rm0, 1));
        rm0 = fmaxf(rm0, __shfl_xor_sync(0xffffffffu, rm0, 2));
        rm1 = fmaxf(rm1, __shfl_xor_sync(0xffffffffu, rm1, 1));
        rm1 = fmaxf(rm1, __shfl_xor_sync(0xffffffffu, rm1, 2));

        float mn0 = fmaxf(mrow0, rm0), mn1 = fmaxf(mrow1, rm1);
        float sc0 = __expf(mrow0 - mn0), sc1 = __expf(mrow1 - mn1);
        mrow0 = mn0; mrow1 = mn1;

        float rs0 = 0.0f, rs1 = 0.0f;
        uint32_t ph[4][4], pl[4][4];
#pragma unroll
        for (int nt = 0; nt < 8; nt++) {
            float p0 = __expf(s[nt][0] - mn0);
            float p1 = __expf(s[nt][1] - mn0);
            float p2 = __expf(s[nt][2] - mn1);
            float p3 = __expf(s[nt][3] - mn1);
            rs0 += p0 + p1;
            rs1 += p2 + p3;
            float h0 = __half2float(__float2half_rn(p0));
            float h1 = __half2float(__float2half_rn(p1));
            float h2 = __half2float(__float2half_rn(p2));
            float h3 = __half2float(__float2half_rn(p3));
            int kt2 = nt >> 1;
            int hi  = (nt & 1) * 2;
            ph[kt2][hi + 0] = pack_h2(h0, h1);
            ph[kt2][hi + 1] = pack_h2(h2, h3);
            pl[kt2][hi + 0] = pack_h2(p0 - h0, p1 - h1);
            pl[kt2][hi + 1] = pack_h2(p2 - h2, p3 - h3);
        }
        rs0 += __shfl_xor_sync(0xffffffffu, rs0, 1);
        rs0 += __shfl_xor_sync(0xffffffffu, rs0, 2);
        rs1 += __shfl_xor_sync(0xffffffffu, rs1, 1);
        rs1 += __shfl_xor_sync(0xffffffffu, rs1, 2);
        l0 = l0 * sc0 + rs0;
        l1 = l1 * sc1 + rs1;

#pragma unroll
        for (int nt = 0; nt < 16; nt++) {
            o[nt][0] *= sc0; o[nt][1] *= sc0;
            o[nt][2] *= sc1; o[nt][3] *= sc1;
        }
        // O += (Ph + Pl) Vf : 2-pass fp16
#pragma unroll
        for (int nt2 = 0; nt2 < 8; nt2++) {
#pragma unroll
            for (int kt2 = 0; kt2 < 4; kt2++) {
                int vr = kt2*16 + vrr;
                int vc = nt2*16 + vcc;
                uint32_t b4[4];
                ldsm_x4t(b4[0], b4[1], b4[2], b4[3], smem_u32(vh + vr*AP + vc));
                mma16816h(o[2*nt2],   ph[kt2], b4[0], b4[1]);
                mma16816h(o[2*nt2+1], ph[kt2], b4[2], b4[3]);
                mma16816h(o[2*nt2],   pl[kt2], b4[0], b4[1]);
                mma16816h(o[2*nt2+1], pl[kt2], b4[2], b4[3]);
            }
        }
        __syncthreads();    // protect buffer (i&1) before it is re-staged
    }

    // store unnormalized partials
    const size_t prow = (size_t)z*MM + (size_t)(b*TT + i0 + rloc);
    if ((lane & 3) == 0) {
        g_pm[prow]     = mrow0;  g_pl[prow]     = l0;
        g_pm[prow + 8] = mrow1;  g_pl[prow + 8] = l1;
    }
#pragma unroll
    for (int nt = 0; nt < 16; nt++) {
        int col = nt*8 + (lane & 3)*2;
        *(float2*)(g_po + prow*HH + col)       = make_float2(o[nt][0], o[nt][1]);
        *(float2*)(g_po + (prow + 8)*HH + col) = make_float2(o[nt][2], o[nt][3]);
    }
}

// ---------------------------------------------------------------------------
// combine the two split-KV partials
// ---------------------------------------------------------------------------
__global__ __launch_bounds__(256) void combine_kernel(float* __restrict__ out)
{
    int i = blockIdx.x * 256 + threadIdx.x;
    int row = i >> 5;
    float m0 = g_pm[row], m1 = g_pm[MM + row];
    float l0 = g_pl[row], l1 = g_pl[MM + row];
    float ms = fmaxf(m0, m1);
    float e0 = __expf(m0 - ms), e1 = __expf(m1 - ms);
    float inv = 1.0f / (l0*e0 + l1*e1);
    float4 a = ((const float4*)g_po)[i];
    float4 bv = ((const float4*)(g_po + (size_t)MM*HH))[i];
    float4 r;
    r.x = (a.x*e0 + bv.x*e1) * inv;
    r.y = (a.y*e0 + bv.y*e1) * inv;
    r.z = (a.z*e0 + bv.z*e1) * inv;
    r.w = (a.w*e0 + bv.w*e1) * inv;
    ((float4*)out)[i] = r;
}

// ---------------------------------------------------------------------------
extern "C" void kernel_launch(void* const* d_in, const int* in_sizes, int n_in,
                              void* d_out, int out_size)
{
    const float* x  = (const float*)d_in[0];
    const float* Wq = (const float*)d_in[1];
    const float* Wk = (const float*)d_in[2];
    const float* Wv = (const float*)d_in[3];
    float* out = (float*)d_out;

    static int attr_set = 0;
    const int qkv_smem  = 2 * QBUF * 2;   // 73728 B
    const int attn_smem = 2 * ABUF * 2;   // 69632 B
    if (!attr_set) {
        cudaFuncSetAttribute(qkv_mma_kernel,
                             cudaFuncAttributeMaxDynamicSharedMemorySize, qkv_smem);
        cudaFuncSetAttribute(attn_kernel,
                             cudaFuncAttributeMaxDynamicSharedMemorySize, attn_smem);
        attr_set = 1;
    }

    convert_x_kernel<<<MM * DD / 4 / 256, 256>>>(x);
    convert_w_kernel<<<dim3(DD * HH / 256, 3), 256>>>(Wq, Wk, Wv);
    qkv_mma_kernel<<<dim3(MM / 128, 3), 256, qkv_smem>>>();
    attn_kernel<<<dim3(TT / 128, BB, 2), 256, attn_smem>>>();
    combine_kernel<<<MM * HH / 4 / 256, 256>>>(out);
}

// round 16
// speedup vs baseline: 1.8176x; 1.8176x over previous
#include <cuda_runtime.h>
#include <cuda_fp16.h>
#include <math.h>
#include <stdint.h>

#define BB 8
#define TT 2048
#define DD 1024
#define HH 128
#define MM (BB*TT)

// ---------------- device-global scratch (allocation-guard safe) ------------
__device__ __half g_xf[MM*DD];              // x fp16
__device__ __half g_wf[3*HH*DD];            // W^T [mat][n][k], fp16
// fp16 attention operands
__device__ __half g_qf[MM*HH];              // post-RoPE, scaled, fp16
__device__ __half g_kf[MM*HH];              // post-RoPE, fp16
__device__ __half g_vf[MM*HH];              // fp16
// split-KV partials: [z][b*TT+row]
__device__ float g_po[2*MM*HH];
__device__ float g_pm[2*MM];
__device__ float g_pl[2*MM];

// ---------------- PTX helpers (base sm_103-safe) ----------------------------
__device__ __forceinline__ uint32_t smem_u32(const void* p) {
    uint32_t a;
    asm("{ .reg .u64 t; cvta.to.shared.u64 t, %1; cvt.u32.u64 %0, t; }"
        : "=r"(a) : "l"(p));
    return a;
}

__device__ __forceinline__ void cp16(uint32_t saddr, const void* g) {
    asm volatile("cp.async.cg.shared.global [%0], [%1], 16;"
                 :: "r"(saddr), "l"(g) : "memory");
}
__device__ __forceinline__ void cp_commit() {
    asm volatile("cp.async.commit_group;" ::: "memory");
}
__device__ __forceinline__ void cp_wait0() {
    asm volatile("cp.async.wait_group 0;" ::: "memory");
}
__device__ __forceinline__ void cp_wait1() {
    asm volatile("cp.async.wait_group 1;" ::: "memory");
}

__device__ __forceinline__ void ldsm_x4(uint32_t& a0, uint32_t& a1,
                                        uint32_t& a2, uint32_t& a3, uint32_t addr) {
    asm volatile("ldmatrix.sync.aligned.m8n8.x4.shared.b16 {%0,%1,%2,%3}, [%4];"
                 : "=r"(a0), "=r"(a1), "=r"(a2), "=r"(a3) : "r"(addr));
}
__device__ __forceinline__ void ldsm_x4t(uint32_t& a0, uint32_t& a1,
                                         uint32_t& a2, uint32_t& a3, uint32_t addr) {
    asm volatile("ldmatrix.sync.aligned.m8n8.x4.trans.shared.b16 {%0,%1,%2,%3}, [%4];"
                 : "=r"(a0), "=r"(a1), "=r"(a2), "=r"(a3) : "r"(addr));
}

// fp16 mma
__device__ __forceinline__ void mma16816h(float* c, const uint32_t* a,
                                          uint32_t b0, uint32_t b1) {
    asm volatile(
        "mma.sync.aligned.m16n8k16.row.col.f32.f16.f16.f32 "
        "{%0,%1,%2,%3}, {%4,%5,%6,%7}, {%8,%9}, {%0,%1,%2,%3};"
        : "+f"(c[0]), "+f"(c[1]), "+f"(c[2]), "+f"(c[3])
        : "r"(a[0]), "r"(a[1]), "r"(a[2]), "r"(a[3]), "r"(b0), "r"(b1));
}

__device__ __forceinline__ uint32_t pack_h2(float a, float b) {
    __half2 h = __floats2half2_rn(a, b);      // x=a (low), y=b (high)
    return *reinterpret_cast<uint32_t*>(&h);
}

// ---------------------------------------------------------------------------
// fp32 -> fp16 conversions
// ---------------------------------------------------------------------------
__global__ __launch_bounds__(256) void convert_x_kernel(const float* __restrict__ x)
{
    int i = blockIdx.x * 256 + threadIdx.x;          // over MM*DD/4
    float4 v = ((const float4*)x)[i];
    uint32_t* ph = (uint32_t*)g_xf;
    ph[2*i]   = pack_h2(v.x, v.y);
    ph[2*i+1] = pack_h2(v.z, v.w);
}

__global__ __launch_bounds__(256) void convert_w_kernel(
    const float* __restrict__ Wq, const float* __restrict__ Wk,
    const float* __restrict__ Wv)
{
    int mat = blockIdx.y;
    const float* __restrict__ W = (mat == 0) ? Wq : ((mat == 1) ? Wk : Wv);
    int i = blockIdx.x * 256 + threadIdx.x;          // 0 .. DD*HH-1
    int k = i >> 7;
    int n = i & 127;
    g_wf[(size_t)mat * HH * DD + (size_t)n * DD + k] = __float2half_rn(W[i]);
}

// ---------------------------------------------------------------------------
// QKV projection: fp16 single-pass mma (xf·Wf) + RoPE epilogue, fp16 outputs.
// grid=(128,3), 256 threads. smem: 2 buffers x (2 tiles x 128 x QP halves)
// ---------------------------------------------------------------------------
#define QP 72
#define QBUF (2*128*QP)

__global__ __launch_bounds__(256) void qkv_mma_kernel()
{
    extern __shared__ __half smq[];

    const int tid = threadIdx.x;
    const int w   = tid >> 5;
    const int lane= tid & 31;
    const int mat = blockIdx.y;
    const int m0  = blockIdx.x * 128;

    const __half* __restrict__ Xf = g_xf + (size_t)m0 * DD;
    const __half* __restrict__ Bw = g_wf + (size_t)mat * HH * DD;

    float c[16][4];
#pragma unroll
    for (int nt = 0; nt < 16; nt++)
#pragma unroll
        for (int e = 0; e < 4; e++) c[nt][e] = 0.0f;

    auto stageq = [&](int buf, int kc) {
        const int kb = kc * 64;
        __half* base = smq + buf * QBUF;
        const __half* srcs[2] = {Xf, Bw};
#pragma unroll
        for (int t = 0; t < 2; t++) {
#pragma unroll
            for (int itr = 0; itr < 4; itr++) {
                int idx = itr * 256 + tid;
                int row = idx >> 3, seg = idx & 7;
                cp16(smem_u32(base + t*128*QP + row*QP + seg*8),
                     srcs[t] + (size_t)row * DD + kb + seg*8);
            }
        }
    };

    stageq(0, 0);
    cp_commit();

    const int brr = (lane & 7) + ((lane >> 4) & 1) * 8;
    const int bcc = (lane & 8);

    for (int kc = 0; kc < 16; kc++) {
        if (kc + 1 < 16) { stageq((kc + 1) & 1, kc + 1); cp_commit(); cp_wait1(); }
        else             { cp_wait0(); }
        __syncthreads();

        __half* base = smq + (kc & 1) * QBUF;
        __half* sxf = base;
        __half* swf = base + 128*QP;

        uint32_t ah[4][4];
        {
            int r = w*16 + (lane & 7) + ((lane >> 3) & 1) * 8;
            int cg = ((lane >> 4) & 1) * 8;
#pragma unroll
            for (int kt = 0; kt < 4; kt++) {
                ldsm_x4(ah[kt][0], ah[kt][1], ah[kt][2], ah[kt][3],
                        smem_u32(sxf + r*QP + kt*16 + cg));
            }
        }

#pragma unroll
        for (int nt2 = 0; nt2 < 8; nt2++) {
#pragma unroll
            for (int kt = 0; kt < 4; kt++) {
                int br = nt2*16 + brr;
                int bc = kt*16 + bcc;
                uint32_t b4[4];
                ldsm_x4(b4[0], b4[1], b4[2], b4[3], smem_u32(swf + br*QP + bc));
                mma16816h(c[2*nt2],   ah[kt], b4[0], b4[1]);
                mma16816h(c[2*nt2+1], ah[kt], b4[2], b4[3]);
            }
        }
        __syncthreads();
    }

    const float qs = (mat == 0) ? 0.08838834764831845f : 1.0f;
    const int rloc = w*16 + (lane >> 2);
    const int m_lo = m0 + rloc;
    const int m_hi = m_lo + 8;
    const float pos0 = (float)(m_lo & (TT - 1));
    const float pos1 = (float)(m_hi & (TT - 1));

    __half* dst = (mat == 0) ? g_qf : (mat == 1) ? g_kf : g_vf;

#pragma unroll
    for (int nt = 0; nt < 16; nt++) {
        int col = nt*8 + (lane & 3)*2;
        float e00 = c[nt][0]*qs, e01 = c[nt][1]*qs;
        float e10 = c[nt][2]*qs, e11 = c[nt][3]*qs;
        if (mat < 2) {
            int p = col >> 1;
            float freq = exp2f(-(float)p * (13.287712379549449f / 64.0f));
            float s0, c0v, s1, c1v;
            sincosf(pos0 * freq, &s0, &c0v);
            sincosf(pos1 * freq, &s1, &c1v);
            float t0 = e00*c0v - e01*s0, t1 = e00*s0 + e01*c0v;
            e00 = t0; e01 = t1;
            t0 = e10*c1v - e11*s1; t1 = e10*s1 + e11*c1v;
            e10 = t0; e11 = t1;
        }
        *(uint32_t*)(dst + (size_t)m_lo*HH + col) = pack_h2(e00, e01);
        *(uint32_t*)(dst + (size_t)m_hi*HH + col) = pack_h2(e10, e11);
    }
}

// ---------------------------------------------------------------------------
// Causal flash attention: fp16, q single-pass / P 2-pass, split-KV z=2,
// cp.async double-buffer. grid=(16,8,2), 256 threads, q-tile 128, k-tile 64.
// smem: 2 buffers x (2 tiles x 64 x AP halves) = 69632 B
// ---------------------------------------------------------------------------
#define AP 136
#define ABUF (2*64*AP)

__global__ __launch_bounds__(256) void attn_kernel()
{
    extern __shared__ __half sma[];

    const int tid = threadIdx.x;
    const int w   = tid >> 5;
    const int lane= tid & 31;
    const int b   = blockIdx.y;
    const int z   = blockIdx.z;
    const int i0  = (gridDim.x - 1 - blockIdx.x) * 128;

    const int rloc = w*16 + (lane >> 2);
    const size_t qrow = (size_t)(b*TT + i0 + rloc) * HH;

    uint32_t qh[8][4];
#pragma unroll
    for (int kt = 0; kt < 8; kt++) {
        int cb = kt*16 + (lane & 3)*2;
        qh[kt][0] = *(const uint32_t*)(g_qf + qrow + cb);
        qh[kt][1] = *(const uint32_t*)(g_qf + qrow + 8*HH + cb);
        qh[kt][2] = *(const uint32_t*)(g_qf + qrow + cb + 8);
        qh[kt][3] = *(const uint32_t*)(g_qf + qrow + 8*HH + cb + 8);
    }

    float o[16][4];
#pragma unroll
    for (int nt = 0; nt < 16; nt++)
#pragma unroll
        for (int e = 0; e < 4; e++) o[nt][e] = 0.0f;
    float mrow0 = -1e30f, mrow1 = -1e30f, l0 = 0.0f, l1 = 0.0f;

    const int ntiles = i0/64 + 2;            // even
    const int htiles = ntiles >> 1;
    const int jt0 = z * htiles;
    const int n = htiles;

    auto stagea = [&](int buf, int jt) {
        const size_t gbase = (size_t)(b*TT + jt*64) * HH;
        __half* base = sma + buf * ABUF;
        const __half* srcs[2] = {g_kf + gbase, g_vf + gbase};
#pragma unroll
        for (int t = 0; t < 2; t++) {
#pragma unroll
            for (int itr = 0; itr < 4; itr++) {
                int idx = itr*256 + tid;
                int row = idx >> 4, seg = idx & 15;
                cp16(smem_u32(base + t*64*AP + row*AP + seg*8),
                     srcs[t] + (size_t)row*HH + seg*8);
            }
        }
    };

    stagea(0, jt0);
    cp_commit();

    const int brr = (lane & 7) + ((lane >> 4) & 1) * 8;   // B-frag row offset
    const int bcc = (lane & 8);                            // B-frag col offset
    const int vrr = (lane & 7) + (lane & 8);               // V-frag row offset
    const int vcc = ((lane >> 4) & 1) * 8;                 // V-frag col offset

    for (int i = 0; i < n; i++) {
        const int jt = jt0 + i;
        const int j0 = jt * 64;

        if (i + 1 < n) { stagea((i + 1) & 1, jt + 1); cp_commit(); cp_wait1(); }
        else           { cp_wait0(); }
        __syncthreads();

        __half* base = sma + (i & 1) * ABUF;
        __half* kh = base;
        __half* vh = base + 64*AP;

        float s[8][4];
#pragma unroll
        for (int nt = 0; nt < 8; nt++)
#pragma unroll
            for (int e = 0; e < 4; e++) s[nt][e] = 0.0f;

        // S = Qf Kf^T : single-pass fp16
#pragma unroll
        for (int nt2 = 0; nt2 < 4; nt2++) {
#pragma unroll
            for (int kt = 0; kt < 8; kt++) {
                int br = nt2*16 + brr;
                int bc = kt*16 + bcc;
                uint32_t b4[4];
                ldsm_x4(b4[0], b4[1], b4[2], b4[3], smem_u32(kh + br*AP + bc));
                mma16816h(s[2*nt2],   qh[kt], b4[0], b4[1]);
                mma16816h(s[2*nt2+1], qh[kt], b4[2], b4[3]);
            }
        }

        if (j0 >= i0) {
            int row0 = i0 + rloc;
            int row1 = row0 + 8;
#pragma unroll
            for (int nt = 0; nt < 8; nt++) {
                int colb = j0 + nt*8 + (lane & 3)*2;
                if (colb     > row0) s[nt][0] = -1e30f;
                if (colb + 1 > row0) s[nt][1] = -1e30f;
                if (colb     > row1) s[nt][2] = -1e30f;
                if (colb + 1 > row1) s[nt][3] = -1e30f;
            }
        }

        float rm0 = -1e30f, rm1 = -1e30f;
#pragma unroll
        for (int nt = 0; nt < 8; nt++) {
            rm0 = fmaxf(rm0, fmaxf(s[nt][0], s[nt][1]));
            rm1 = fmaxf(rm1, fmaxf(s[nt][2], s[nt][3]));
        }
        rm0 = fmaxf(rm0, __shfl_xor_sync(0xffffffffu, rm0, 1));
        rm0 = fmaxf(rm0, __shfl_xor_sync(0xffffffffu, rm0, 2));
        rm1 = fmaxf(rm1, __shfl_xor_sync(0xffffffffu, rm1, 1));
        rm1 = fmaxf(rm1, __shfl_xor_sync(0xffffffffu, rm1, 2));

        float mn0 = fmaxf(mrow0, rm0), mn1 = fmaxf(mrow1, rm1);
        float sc0 = __expf(mrow0 - mn0), sc1 = __expf(mrow1 - mn1);
        mrow0 = mn0; mrow1 = mn1;

        float rs0 = 0.0f, rs1 = 0.0f;
        uint32_t ph[4][4], pl[4][4];
#pragma unroll
        for (int nt = 0; nt < 8; nt++) {
            float p0 = __expf(s[nt][0] - mn0);
            float p1 = __expf(s[nt][1] - mn0);
            float p2 = __expf(s[nt][2] - mn1);
            float p3 = __expf(s[nt][3] - mn1);
            rs0 += p0 + p1;
            rs1 += p2 + p3;
            float h0 = __half2float(__float2half_rn(p0));
            float h1 = __half2float(__float2half_rn(p1));
            float h2 = __half2float(__float2half_rn(p2));
            float h3 = __half2float(__float2half_rn(p3));
            int kt2 = nt >> 1;
            int hi  = (nt & 1) * 2;
            ph[kt2][hi + 0] = pack_h2(h0, h1);
            ph[kt2][hi + 1] = pack_h2(h2, h3);
            pl[kt2][hi + 0] = pack_h2(p0 - h0, p1 - h1);
            pl[kt2][hi + 1] = pack_h2(p2 - h2, p3 - h3);
        }
        rs0 += __shfl_xor_sync(0xffffffffu, rs0, 1);
        rs0 += __shfl_xor_sync(0xffffffffu, rs0, 2);
        rs1 += __shfl_xor_sync(0xffffffffu, rs1, 1);
        rs1 += __shfl_xor_sync(0xffffffffu, rs1, 2);
        l0 = l0 * sc0 + rs0;
        l1 = l1 * sc1 + rs1;

#pragma unroll
        for (int nt = 0; nt < 16; nt++) {
            o[nt][0] *= sc0; o[nt][1] *= sc0;
            o[nt][2] *= sc1; o[nt][3] *= sc1;
        }
        // O += (Ph + Pl) Vf : 2-pass fp16
#pragma unroll
        for (int nt2 = 0; nt2 < 8; nt2++) {
#pragma unroll
            for (int kt2 = 0; kt2 < 4; kt2++) {
                int vr = kt2*16 + vrr;
                int vc = nt2*16 + vcc;
                uint32_t b4[4];
                ldsm_x4t(b4[0], b4[1], b4[2], b4[3], smem_u32(vh + vr*AP + vc));
                mma16816h(o[2*nt2],   ph[kt2], b4[0], b4[1]);
                mma16816h(o[2*nt2+1], ph[kt2], b4[2], b4[3]);
                mma16816h(o[2*nt2],   pl[kt2], b4[0], b4[1]);
                mma16816h(o[2*nt2+1], pl[kt2], b4[2], b4[3]);
            }
        }
        __syncthreads();    // protect buffer (i&1) before it is re-staged
    }

    // store unnormalized partials
    const size_t prow = (size_t)z*MM + (size_t)(b*TT + i0 + rloc);
    if ((lane & 3) == 0) {
        g_pm[prow]     = mrow0;  g_pl[prow]     = l0;
        g_pm[prow + 8] = mrow1;  g_pl[prow + 8] = l1;
    }
#pragma unroll
    for (int nt = 0; nt < 16; nt++) {
        int col = nt*8 + (lane & 3)*2;
        *(float2*)(g_po + prow*HH + col)       = make_float2(o[nt][0], o[nt][1]);
        *(float2*)(g_po + (prow + 8)*HH + col) = make_float2(o[nt][2], o[nt][3]);
    }
}

// ---------------------------------------------------------------------------
// combine the two split-KV partials
// ---------------------------------------------------------------------------
__global__ __launch_bounds__(256) void combine_kernel(float* __restrict__ out)
{
    int i = blockIdx.x * 256 + threadIdx.x;
    int row = i >> 5;
    float m0 = g_pm[row], m1 = g_pm[MM + row];
    float l0 = g_pl[row], l1 = g_pl[MM + row];
    float ms = fmaxf(m0, m1);
    float e0 = __expf(m0 - ms), e1 = __expf(m1 - ms);
    float inv = 1.0f / (l0*e0 + l1*e1);
    float4 a = ((const float4*)g_po)[i];
    float4 bv = ((const float4*)(g_po + (size_t)MM*HH))[i];
    float4 r;
    r.x = (a.x*e0 + bv.x*e1) * inv;
    r.y = (a.y*e0 + bv.y*e1) * inv;
    r.z = (a.z*e0 + bv.z*e1) * inv;
    r.w = (a.w*e0 + bv.w*e1) * inv;
    ((float4*)out)[i] = r;
}

// ---------------------------------------------------------------------------
extern "C" void kernel_launch(void* const* d_in, const int* in_sizes, int n_in,
                              void* d_out, int out_size)
{
    const float* x  = (const float*)d_in[0];
    const float* Wq = (const float*)d_in[1];
    const float* Wk = (const float*)d_in[2];
    const float* Wv = (const float*)d_in[3];
    float* out = (float*)d_out;

    static int attr_set = 0;
    const int qkv_smem  = 2 * QBUF * 2;   // 73728 B
    const int attn_smem = 2 * ABUF * 2;   // 69632 B
    if (!attr_set) {
        cudaFuncSetAttribute(qkv_mma_kernel,
                             cudaFuncAttributeMaxDynamicSharedMemorySize, qkv_smem);
        cudaFuncSetAttribute(attn_kernel,
                             cudaFuncAttributeMaxDynamicSharedMemorySize, attn_smem);
        attr_set = 1;
    }

    convert_x_kernel<<<MM * DD / 4 / 256, 256>>>(x);
    convert_w_kernel<<<dim3(DD * HH / 256, 3), 256>>>(Wq, Wk, Wv);
    qkv_mma_kernel<<<dim3(MM / 128, 3), 256, qkv_smem>>>();
    attn_kernel<<<dim3(TT / 128, BB, 2), 256, attn_smem>>>();
    combine_kernel<<<MM * HH / 4 / 256, 256>>>(out);
}